// round 11
// baseline (speedup 1.0000x reference)
#include <cuda_runtime.h>
#include <cstdint>

#define N_NODES 100000
#define N_EDGES 1250000
#define D 64
#define ZBLKS ((N_NODES + 1023) / 1024)   // 98

// Scratch (static device globals — no allocation allowed)
__device__ __align__(128) float g_a1[(size_t)N_NODES * D];  // A1 = agg(x)
__device__ __align__(128) float g_a2[(size_t)N_NODES * D];  // A2 = agg(A1)
__device__ float g_W2[D * D];                  // W @ W
__device__ float g_bW[D];                      // b @ W^T
__device__ int   g_deg[N_NODES];
__device__ int   g_off[N_NODES + 4];
__device__ int   g_cur[N_NODES];
__device__ int   g_srcs[N_EDGES];
__device__ int   g_bsum[ZBLKS];
__device__ int   g_boff[ZBLKS];
__device__ int   g_is64;

// ---------------------------------------------------------------------------
// Fused init: blocks [0,98) zero g_deg; [98,114) compute W2; 114: bW + detect.
// ---------------------------------------------------------------------------
__global__ void init2_kernel(const unsigned* __restrict__ ei,
                             const float* __restrict__ W,
                             const float* __restrict__ b) {
    int t = threadIdx.x;                 // 256
    int bid = blockIdx.x;
    if (bid < ZBLKS) {
        int i4 = bid * 1024 + t * 4;
        if (i4 < N_NODES)
            *reinterpret_cast<int4*>(&g_deg[i4]) = make_int4(0, 0, 0, 0);
        return;
    }
    __shared__ float Wsh[D * D];
    #pragma unroll
    for (int i = t; i < D * D; i += 256) Wsh[i] = W[i];
    __syncthreads();
    if (bid < ZBLKS + 16) {
        int o = (bid - ZBLKS) * 256 + t;
        int j = o >> 6, k = o & 63;
        float s = 0.f;
        #pragma unroll
        for (int m = 0; m < D; m++) s += Wsh[j * D + m] * Wsh[m * D + k];
        g_W2[o] = s;
    } else {
        if (t < D) {
            float s = 0.f;
            #pragma unroll
            for (int k = 0; k < D; k++) s += b[k] * Wsh[t * D + k];
            g_bW[t] = s;
        } else if (t == 64) {
            int all0 = 1;
            #pragma unroll 1
            for (int k = 0; k < 64; k++) {
                if (ei[2 * k + 1] != 0u) { all0 = 0; break; }
            }
            g_is64 = all0;
        }
    }
}

// ---------------------------------------------------------------------------
// Histogram over dst (4 edges/thread, vectorized loads).
// ---------------------------------------------------------------------------
__global__ void hist_kernel(const void* __restrict__ ei) {
    int q = blockIdx.x * blockDim.x + threadIdx.x;
    int e = q * 4;
    if (e >= N_EDGES) return;
    int d0, d1, d2, d3;
    if (g_is64) {
        const longlong2* p = reinterpret_cast<const longlong2*>(
            (const long long*)ei + N_EDGES + e);
        longlong2 a = __ldg(p), c = __ldg(p + 1);
        d0 = (int)a.x; d1 = (int)a.y; d2 = (int)c.x; d3 = (int)c.y;
    } else {
        int4 a = __ldg(reinterpret_cast<const int4*>((const int*)ei + N_EDGES + e));
        d0 = a.x; d1 = a.y; d2 = a.z; d3 = a.w;
    }
    atomicAdd(&g_deg[d0], 1);
    atomicAdd(&g_deg[d1], 1);
    atomicAdd(&g_deg[d2], 1);
    atomicAdd(&g_deg[d3], 1);
}

// ---------------------------------------------------------------------------
// Scan trio: per-block sums (1024/block) -> scan of 98 sums -> offsets.
// ---------------------------------------------------------------------------
__global__ void partial_kernel() {
    __shared__ int ws[8];
    int t = threadIdx.x;
    int i4 = blockIdx.x * 1024 + t * 4;
    int v = 0;
    if (i4 < N_NODES) {
        int4 a = *reinterpret_cast<const int4*>(&g_deg[i4]);
        v = a.x + a.y + a.z + a.w;
    }
    #pragma unroll
    for (int o = 16; o > 0; o >>= 1) v += __shfl_down_sync(0xffffffffu, v, o);
    if ((t & 31) == 0) ws[t >> 5] = v;
    __syncthreads();
    if (t == 0) {
        int s = 0;
        #pragma unroll
        for (int i = 0; i < 8; i++) s += ws[i];
        g_bsum[blockIdx.x] = s;
    }
}

__global__ void scan_bsums_kernel() {
    __shared__ int ws[4];
    int t = threadIdx.x;           // 128 threads
    int lane = t & 31, wid = t >> 5;
    int v = (t < ZBLKS) ? g_bsum[t] : 0;
    int incl = v;
    #pragma unroll
    for (int o = 1; o < 32; o <<= 1) {
        int n = __shfl_up_sync(0xffffffffu, incl, o);
        if (lane >= o) incl += n;
    }
    if (lane == 31) ws[wid] = incl;
    __syncthreads();
    if (wid == 0 && lane < 4) {
        int w = ws[lane];
        #pragma unroll
        for (int o = 1; o < 4; o <<= 1) {
            int n = __shfl_up_sync(0x0000000fu, w, o);
            if (lane >= o) w += n;
        }
        ws[lane] = w;
    }
    __syncthreads();
    int excl = incl - v + (wid ? ws[wid - 1] : 0);
    if (t < ZBLKS) g_boff[t] = excl;
    if (t == 0) g_off[N_NODES] = N_EDGES;
}

__global__ void write_off_kernel() {
    __shared__ int ws[8];
    int t = threadIdx.x;
    int lane = t & 31, wid = t >> 5;
    int i4 = blockIdx.x * 1024 + t * 4;
    int4 a = make_int4(0, 0, 0, 0);
    if (i4 < N_NODES) a = *reinterpret_cast<const int4*>(&g_deg[i4]);
    int s4 = a.x + a.y + a.z + a.w;
    int incl = s4;
    #pragma unroll
    for (int o = 1; o < 32; o <<= 1) {
        int n = __shfl_up_sync(0xffffffffu, incl, o);
        if (lane >= o) incl += n;
    }
    if (lane == 31) ws[wid] = incl;
    __syncthreads();
    if (wid == 0 && lane < 8) {
        int w = ws[lane];
        #pragma unroll
        for (int o = 1; o < 8; o <<= 1) {
            int n = __shfl_up_sync(0x000000ffu, w, o);
            if (lane >= o) w += n;
        }
        ws[lane] = w;
    }
    __syncthreads();
    int base = incl - s4 + (wid ? ws[wid - 1] : 0) + g_boff[blockIdx.x];
    if (i4 < N_NODES) {
        int4 o;
        o.x = base;
        o.y = base + a.x;
        o.z = base + a.x + a.y;
        o.w = base + a.x + a.y + a.z;
        *reinterpret_cast<int4*>(&g_off[i4]) = o;
        *reinterpret_cast<int4*>(&g_cur[i4]) = o;
    }
}

// ---------------------------------------------------------------------------
// Fill CSR adjacency (4 edges/thread).
// ---------------------------------------------------------------------------
__global__ void fill_kernel(const void* __restrict__ ei) {
    int q = blockIdx.x * blockDim.x + threadIdx.x;
    int e = q * 4;
    if (e >= N_EDGES) return;
    int s0, s1, s2, s3, d0, d1, d2, d3;
    if (g_is64) {
        const longlong2* ps = reinterpret_cast<const longlong2*>((const long long*)ei + e);
        const longlong2* pd = reinterpret_cast<const longlong2*>((const long long*)ei + N_EDGES + e);
        longlong2 a = __ldg(ps), c = __ldg(ps + 1);
        longlong2 u = __ldg(pd), w = __ldg(pd + 1);
        s0 = (int)a.x; s1 = (int)a.y; s2 = (int)c.x; s3 = (int)c.y;
        d0 = (int)u.x; d1 = (int)u.y; d2 = (int)w.x; d3 = (int)w.y;
    } else {
        int4 a = __ldg(reinterpret_cast<const int4*>((const int*)ei + e));
        int4 u = __ldg(reinterpret_cast<const int4*>((const int*)ei + N_EDGES + e));
        s0 = a.x; s1 = a.y; s2 = a.z; s3 = a.w;
        d0 = u.x; d1 = u.y; d2 = u.z; d3 = u.w;
    }
    g_srcs[atomicAdd(&g_cur[d0], 1)] = s0;
    g_srcs[atomicAdd(&g_cur[d1], 1)] = s1;
    g_srcs[atomicAdd(&g_cur[d2], 1)] = s2;
    g_srcs[atomicAdd(&g_cur[d3], 1)] = s3;
}

// ---------------------------------------------------------------------------
// Gather (fp32): phase 0: x -> g_a1, phase 1: g_a1 -> g_a2.
// 16 lanes per node (one float4 each). Simple loop, compiler-pipelined
// (low register pressure; ptxas extracts MLP via unroll).
// ---------------------------------------------------------------------------
__global__ void gather_kernel(const float* __restrict__ x, int phase) {
    int t = blockIdx.x * blockDim.x + threadIdx.x;
    int node = t >> 4;
    int c = t & 15;
    if (node >= N_NODES) return;

    const float* in = phase ? g_a1 : x;
    float* outp     = phase ? g_a2 : g_a1;

    int beg = __ldg(&g_off[node]);
    int end = __ldg(&g_off[node + 1]);

    float4 acc = make_float4(0.f, 0.f, 0.f, 0.f);
    #pragma unroll 8
    for (int e = beg; e < end; e++) {
        int s = __ldg(&g_srcs[e]);
        float4 v = *reinterpret_cast<const float4*>(in + (size_t)s * D + c * 4);
        acc.x += v.x; acc.y += v.y; acc.z += v.z; acc.w += v.w;
    }
    *reinterpret_cast<float4*>(outp + (size_t)node * D + c * 4) = acc;
}

// ---------------------------------------------------------------------------
// Dual GEMM per 64-row tile:
//   phase 1:  hid = A1 @ W^T  + b
//   phase 2:  out = A2 @ W2^T + deg*bW + b
// 4x4 register tile, fma.rn.f32x2 (FFMA2).
// ---------------------------------------------------------------------------
#define SROW 68

__device__ __forceinline__ void stage_a_tile(float* As, const float* __restrict__ src,
                                             int row0, int t) {
    #pragma unroll
    for (int i = t; i < 64 * 16; i += 256) {
        int r = i >> 4, k4 = i & 15;
        int row = row0 + r;
        float4 v = make_float4(0.f, 0.f, 0.f, 0.f);
        if (row < N_NODES)
            v = reinterpret_cast<const float4*>(src)[(size_t)row * 16 + k4];
        *reinterpret_cast<float4*>(&As[r * SROW + k4 * 4]) = v;
    }
}

__device__ __forceinline__ void gemm_tile(const float* As, const float* Ws,
                                          unsigned long long acc[4][4],
                                          int tx, int ty) {
    #pragma unroll 4
    for (int k4 = 0; k4 < 16; k4++) {
        ulonglong2 a[4], w[4];
        #pragma unroll
        for (int ri = 0; ri < 4; ri++)
            a[ri] = *reinterpret_cast<const ulonglong2*>(&As[(ty * 4 + ri) * SROW + k4 * 4]);
        #pragma unroll
        for (int ji = 0; ji < 4; ji++)
            w[ji] = *reinterpret_cast<const ulonglong2*>(&Ws[(tx + 16 * ji) * SROW + k4 * 4]);
        #pragma unroll
        for (int ri = 0; ri < 4; ri++)
            #pragma unroll
            for (int ji = 0; ji < 4; ji++) {
                asm("fma.rn.f32x2 %0, %1, %2, %0;"
                    : "+l"(acc[ri][ji]) : "l"(a[ri].x), "l"(w[ji].x));
                asm("fma.rn.f32x2 %0, %1, %2, %0;"
                    : "+l"(acc[ri][ji]) : "l"(a[ri].y), "l"(w[ji].y));
            }
    }
}

__global__ __launch_bounds__(256) void dual_linear_kernel(
        float* __restrict__ hid, float* __restrict__ out,
        const float* __restrict__ W, const float* __restrict__ b) {
    __shared__ __align__(16) float As[64 * SROW];
    __shared__ __align__(16) float Ws[64 * SROW];

    const int t = threadIdx.x;           // 256 threads
    const int row0 = blockIdx.x * 64;
    const int tx = t & 15;
    const int ty = t >> 4;

    // ---- phase 1: hid = A1 @ W^T + b ----
    #pragma unroll
    for (int i = t; i < 64 * 16; i += 256) {
        int j = i >> 4, k4 = i & 15;
        *reinterpret_cast<float4*>(&Ws[j * SROW + k4 * 4]) =
            reinterpret_cast<const float4*>(W)[j * 16 + k4];
    }
    stage_a_tile(As, g_a1, row0, t);
    __syncthreads();

    {
        unsigned long long acc[4][4];
        #pragma unroll
        for (int ri = 0; ri < 4; ri++)
            #pragma unroll
            for (int ji = 0; ji < 4; ji++) acc[ri][ji] = 0ull;
        gemm_tile(As, Ws, acc, tx, ty);
        float bj[4];
        #pragma unroll
        for (int ji = 0; ji < 4; ji++) bj[ji] = __ldg(&b[tx + 16 * ji]);
        #pragma unroll
        for (int ri = 0; ri < 4; ri++) {
            int row = row0 + ty * 4 + ri;
            if (row < N_NODES) {
                #pragma unroll
                for (int ji = 0; ji < 4; ji++) {
                    float lo, hi;
                    asm("mov.b64 {%0, %1}, %2;" : "=f"(lo), "=f"(hi) : "l"(acc[ri][ji]));
                    hid[(size_t)row * D + tx + 16 * ji] = lo + hi + bj[ji];
                }
            }
        }
    }
    __syncthreads();

    // ---- phase 2: out = A2 @ W2^T + deg*bW + b ----
    #pragma unroll
    for (int i = t; i < 64 * 16; i += 256) {
        int j = i >> 4, k4 = i & 15;
        *reinterpret_cast<float4*>(&Ws[j * SROW + k4 * 4]) =
            reinterpret_cast<const float4*>(g_W2)[j * 16 + k4];
    }
    stage_a_tile(As, g_a2, row0, t);
    __syncthreads();

    {
        unsigned long long acc[4][4];
        #pragma unroll
        for (int ri = 0; ri < 4; ri++)
            #pragma unroll
            for (int ji = 0; ji < 4; ji++) acc[ri][ji] = 0ull;
        gemm_tile(As, Ws, acc, tx, ty);
        float bj[4], bWj[4];
        #pragma unroll
        for (int ji = 0; ji < 4; ji++) {
            bj[ji]  = __ldg(&b[tx + 16 * ji]);
            bWj[ji] = __ldg(&g_bW[tx + 16 * ji]);
        }
        #pragma unroll
        for (int ri = 0; ri < 4; ri++) {
            int row = row0 + ty * 4 + ri;
            if (row < N_NODES) {
                float degf = __int2float_rn(__ldg(&g_deg[row]));
                #pragma unroll
                for (int ji = 0; ji < 4; ji++) {
                    float lo, hi;
                    asm("mov.b64 {%0, %1}, %2;" : "=f"(lo), "=f"(hi) : "l"(acc[ri][ji]));
                    out[(size_t)row * D + tx + 16 * ji] = lo + hi + degf * bWj[ji] + bj[ji];
                }
            }
        }
    }
}

// ---------------------------------------------------------------------------
extern "C" void kernel_launch(void* const* d_in, const int* in_sizes, int n_in,
                              void* d_out, int out_size) {
    const float* x  = (const float*)d_in[0];
    const void*  ei = d_in[1];
    const float* W1 = (const float*)d_in[2];
    const float* b1 = (const float*)d_in[3];

    float* out = (float*)d_out;                      // (out, hid) flattened
    float* hid = out + (size_t)N_NODES * D;

    const int E4BLK = (N_EDGES / 4 + 255) / 256;     // 1221
    const int GBLK  = (N_NODES * 16 + 255) / 256;    // 6250
    const int FBLK  = (N_NODES + 63) / 64;           // 1563

    init2_kernel<<<ZBLKS + 17, 256>>>((const unsigned*)ei, W1, b1);
    hist_kernel<<<E4BLK, 256>>>(ei);
    partial_kernel<<<ZBLKS, 256>>>();
    scan_bsums_kernel<<<1, 128>>>();
    write_off_kernel<<<ZBLKS, 256>>>();
    fill_kernel<<<E4BLK, 256>>>(ei);
    gather_kernel<<<GBLK, 256>>>(x, 0);              // A1 = agg(x)
    gather_kernel<<<GBLK, 256>>>(x, 1);              // A2 = agg(A1)
    dual_linear_kernel<<<FBLK, 256>>>(hid, out, W1, b1);
}

// round 12
// speedup vs baseline: 1.0653x; 1.0653x over previous
#include <cuda_runtime.h>
#include <cstdint>

#define N_NODES 100000
#define N_EDGES 1250000
#define D 64
#define CAP 96                            // bucket capacity per node; P(deg>96)~1e-50
#define ZBLKS ((N_NODES + 1023) / 1024)   // 98

// Scratch (static device globals — no allocation allowed)
__device__ __align__(128) float g_a1[(size_t)N_NODES * D];  // A1 = agg(x)
__device__ __align__(128) float g_a2[(size_t)N_NODES * D];  // A2 = agg(A1)
__device__ int   g_slot[(size_t)N_NODES * CAP];             // bucketed src ids
__device__ int   g_cnt[N_NODES];                            // degree / cursor
__device__ float g_W2[D * D];                  // W @ W
__device__ float g_bW[D];                      // b @ W^T
__device__ int   g_is64;

// ---------------------------------------------------------------------------
// Fused init: blocks [0,98) zero g_cnt; [98,114) compute W2; 114: bW + detect.
// ---------------------------------------------------------------------------
__global__ void init2_kernel(const unsigned* __restrict__ ei,
                             const float* __restrict__ W,
                             const float* __restrict__ b) {
    int t = threadIdx.x;                 // 256
    int bid = blockIdx.x;
    if (bid < ZBLKS) {
        int i4 = bid * 1024 + t * 4;
        if (i4 < N_NODES)
            *reinterpret_cast<int4*>(&g_cnt[i4]) = make_int4(0, 0, 0, 0);
        return;
    }
    __shared__ float Wsh[D * D];
    #pragma unroll
    for (int i = t; i < D * D; i += 256) Wsh[i] = W[i];
    __syncthreads();
    if (bid < ZBLKS + 16) {
        int o = (bid - ZBLKS) * 256 + t;
        int j = o >> 6, k = o & 63;
        float s = 0.f;
        #pragma unroll
        for (int m = 0; m < D; m++) s += Wsh[j * D + m] * Wsh[m * D + k];
        g_W2[o] = s;
    } else {
        if (t < D) {
            float s = 0.f;
            #pragma unroll
            for (int k = 0; k < D; k++) s += b[k] * Wsh[t * D + k];
            g_bW[t] = s;
        } else if (t == 64) {
            int all0 = 1;
            #pragma unroll 1
            for (int k = 0; k < 64; k++) {
                if (ei[2 * k + 1] != 0u) { all0 = 0; break; }
            }
            g_is64 = all0;
        }
    }
}

// ---------------------------------------------------------------------------
// One-pass bucket fill: slot[dst*CAP + pos] = src. 4 edges/thread.
// ---------------------------------------------------------------------------
__global__ void bucket_kernel(const void* __restrict__ ei) {
    int q = blockIdx.x * blockDim.x + threadIdx.x;
    int e = q * 4;
    if (e >= N_EDGES) return;
    int s0, s1, s2, s3, d0, d1, d2, d3;
    if (g_is64) {
        const longlong2* ps = reinterpret_cast<const longlong2*>((const long long*)ei + e);
        const longlong2* pd = reinterpret_cast<const longlong2*>((const long long*)ei + N_EDGES + e);
        longlong2 a = __ldg(ps), c = __ldg(ps + 1);
        longlong2 u = __ldg(pd), w = __ldg(pd + 1);
        s0 = (int)a.x; s1 = (int)a.y; s2 = (int)c.x; s3 = (int)c.y;
        d0 = (int)u.x; d1 = (int)u.y; d2 = (int)w.x; d3 = (int)w.y;
    } else {
        int4 a = __ldg(reinterpret_cast<const int4*>((const int*)ei + e));
        int4 u = __ldg(reinterpret_cast<const int4*>((const int*)ei + N_EDGES + e));
        s0 = a.x; s1 = a.y; s2 = a.z; s3 = a.w;
        d0 = u.x; d1 = u.y; d2 = u.z; d3 = u.w;
    }
    int p0 = atomicAdd(&g_cnt[d0], 1);
    int p1 = atomicAdd(&g_cnt[d1], 1);
    int p2 = atomicAdd(&g_cnt[d2], 1);
    int p3 = atomicAdd(&g_cnt[d3], 1);
    if (p0 < CAP) g_slot[(size_t)d0 * CAP + p0] = s0;
    if (p1 < CAP) g_slot[(size_t)d1 * CAP + p1] = s1;
    if (p2 < CAP) g_slot[(size_t)d2 * CAP + p2] = s2;
    if (p3 < CAP) g_slot[(size_t)d3 * CAP + p3] = s3;
}

// ---------------------------------------------------------------------------
// Gather (fp32): phase 0: x -> g_a1, phase 1: g_a1 -> g_a2.
// 16 lanes per node (one float4 each); simple compiler-pipelined loop.
// ---------------------------------------------------------------------------
__global__ void gather_kernel(const float* __restrict__ x, int phase) {
    int t = blockIdx.x * blockDim.x + threadIdx.x;
    int node = t >> 4;
    int c = t & 15;
    if (node >= N_NODES) return;

    const float* in = phase ? g_a1 : x;
    float* outp     = phase ? g_a2 : g_a1;

    int cnt = __ldg(&g_cnt[node]);
    if (cnt > CAP) cnt = CAP;
    const int* slots = g_slot + (size_t)node * CAP;

    float4 acc = make_float4(0.f, 0.f, 0.f, 0.f);
    #pragma unroll 8
    for (int e = 0; e < cnt; e++) {
        int s = __ldg(&slots[e]);
        float4 v = *reinterpret_cast<const float4*>(in + (size_t)s * D + c * 4);
        acc.x += v.x; acc.y += v.y; acc.z += v.z; acc.w += v.w;
    }
    *reinterpret_cast<float4*>(outp + (size_t)node * D + c * 4) = acc;
}

// ---------------------------------------------------------------------------
// Dual GEMM per 64-row tile:
//   phase 1:  hid = A1 @ W^T  + b
//   phase 2:  out = A2 @ W2^T + deg*bW + b
// 4x4 register tile, fma.rn.f32x2 (FFMA2).
// ---------------------------------------------------------------------------
#define SROW 68

__device__ __forceinline__ void stage_a_tile(float* As, const float* __restrict__ src,
                                             int row0, int t) {
    #pragma unroll
    for (int i = t; i < 64 * 16; i += 256) {
        int r = i >> 4, k4 = i & 15;
        int row = row0 + r;
        float4 v = make_float4(0.f, 0.f, 0.f, 0.f);
        if (row < N_NODES)
            v = reinterpret_cast<const float4*>(src)[(size_t)row * 16 + k4];
        *reinterpret_cast<float4*>(&As[r * SROW + k4 * 4]) = v;
    }
}

__device__ __forceinline__ void gemm_tile(const float* As, const float* Ws,
                                          unsigned long long acc[4][4],
                                          int tx, int ty) {
    #pragma unroll 4
    for (int k4 = 0; k4 < 16; k4++) {
        ulonglong2 a[4], w[4];
        #pragma unroll
        for (int ri = 0; ri < 4; ri++)
            a[ri] = *reinterpret_cast<const ulonglong2*>(&As[(ty * 4 + ri) * SROW + k4 * 4]);
        #pragma unroll
        for (int ji = 0; ji < 4; ji++)
            w[ji] = *reinterpret_cast<const ulonglong2*>(&Ws[(tx + 16 * ji) * SROW + k4 * 4]);
        #pragma unroll
        for (int ri = 0; ri < 4; ri++)
            #pragma unroll
            for (int ji = 0; ji < 4; ji++) {
                asm("fma.rn.f32x2 %0, %1, %2, %0;"
                    : "+l"(acc[ri][ji]) : "l"(a[ri].x), "l"(w[ji].x));
                asm("fma.rn.f32x2 %0, %1, %2, %0;"
                    : "+l"(acc[ri][ji]) : "l"(a[ri].y), "l"(w[ji].y));
            }
    }
}

__global__ __launch_bounds__(256) void dual_linear_kernel(
        float* __restrict__ hid, float* __restrict__ out,
        const float* __restrict__ W, const float* __restrict__ b) {
    __shared__ __align__(16) float As[64 * SROW];
    __shared__ __align__(16) float Ws[64 * SROW];

    const int t = threadIdx.x;           // 256 threads
    const int row0 = blockIdx.x * 64;
    const int tx = t & 15;
    const int ty = t >> 4;

    // ---- phase 1: hid = A1 @ W^T + b ----
    #pragma unroll
    for (int i = t; i < 64 * 16; i += 256) {
        int j = i >> 4, k4 = i & 15;
        *reinterpret_cast<float4*>(&Ws[j * SROW + k4 * 4]) =
            reinterpret_cast<const float4*>(W)[j * 16 + k4];
    }
    stage_a_tile(As, g_a1, row0, t);
    __syncthreads();

    {
        unsigned long long acc[4][4];
        #pragma unroll
        for (int ri = 0; ri < 4; ri++)
            #pragma unroll
            for (int ji = 0; ji < 4; ji++) acc[ri][ji] = 0ull;
        gemm_tile(As, Ws, acc, tx, ty);
        float bj[4];
        #pragma unroll
        for (int ji = 0; ji < 4; ji++) bj[ji] = __ldg(&b[tx + 16 * ji]);
        #pragma unroll
        for (int ri = 0; ri < 4; ri++) {
            int row = row0 + ty * 4 + ri;
            if (row < N_NODES) {
                #pragma unroll
                for (int ji = 0; ji < 4; ji++) {
                    float lo, hi;
                    asm("mov.b64 {%0, %1}, %2;" : "=f"(lo), "=f"(hi) : "l"(acc[ri][ji]));
                    hid[(size_t)row * D + tx + 16 * ji] = lo + hi + bj[ji];
                }
            }
        }
    }
    __syncthreads();

    // ---- phase 2: out = A2 @ W2^T + deg*bW + b ----
    #pragma unroll
    for (int i = t; i < 64 * 16; i += 256) {
        int j = i >> 4, k4 = i & 15;
        *reinterpret_cast<float4*>(&Ws[j * SROW + k4 * 4]) =
            reinterpret_cast<const float4*>(g_W2)[j * 16 + k4];
    }
    stage_a_tile(As, g_a2, row0, t);
    __syncthreads();

    {
        unsigned long long acc[4][4];
        #pragma unroll
        for (int ri = 0; ri < 4; ri++)
            #pragma unroll
            for (int ji = 0; ji < 4; ji++) acc[ri][ji] = 0ull;
        gemm_tile(As, Ws, acc, tx, ty);
        float bj[4], bWj[4];
        #pragma unroll
        for (int ji = 0; ji < 4; ji++) {
            bj[ji]  = __ldg(&b[tx + 16 * ji]);
            bWj[ji] = __ldg(&g_bW[tx + 16 * ji]);
        }
        #pragma unroll
        for (int ri = 0; ri < 4; ri++) {
            int row = row0 + ty * 4 + ri;
            if (row < N_NODES) {
                float degf = __int2float_rn(__ldg(&g_cnt[row]));
                #pragma unroll
                for (int ji = 0; ji < 4; ji++) {
                    float lo, hi;
                    asm("mov.b64 {%0, %1}, %2;" : "=f"(lo), "=f"(hi) : "l"(acc[ri][ji]));
                    out[(size_t)row * D + tx + 16 * ji] = lo + hi + degf * bWj[ji] + bj[ji];
                }
            }
        }
    }
}

// ---------------------------------------------------------------------------
extern "C" void kernel_launch(void* const* d_in, const int* in_sizes, int n_in,
                              void* d_out, int out_size) {
    const float* x  = (const float*)d_in[0];
    const void*  ei = d_in[1];
    const float* W1 = (const float*)d_in[2];
    const float* b1 = (const float*)d_in[3];

    float* out = (float*)d_out;                      // (out, hid) flattened
    float* hid = out + (size_t)N_NODES * D;

    const int E4BLK = (N_EDGES / 4 + 255) / 256;     // 1221
    const int GBLK  = (N_NODES * 16 + 255) / 256;    // 6250
    const int FBLK  = (N_NODES + 63) / 64;           // 1563

    init2_kernel<<<ZBLKS + 17, 256>>>((const unsigned*)ei, W1, b1);
    bucket_kernel<<<E4BLK, 256>>>(ei);
    gather_kernel<<<GBLK, 256>>>(x, 0);              // A1 = agg(x)
    gather_kernel<<<GBLK, 256>>>(x, 1);              // A2 = agg(A1)
    dual_linear_kernel<<<FBLK, 256>>>(hid, out, W1, b1);
}

// round 13
// speedup vs baseline: 1.0809x; 1.0146x over previous
#include <cuda_runtime.h>
#include <cstdint>

#define N_NODES 100000
#define N_EDGES 1250000
#define D 64
#define CAP 96                            // bucket capacity; P(deg>96)~1e-50; int4-aligned
#define ZBLKS ((N_NODES + 1023) / 1024)   // 98

// Scratch (static device globals — no allocation allowed)
__device__ __align__(128) float g_a1[(size_t)N_NODES * D];  // A1 = agg(x)
__device__ __align__(128) float g_a2[(size_t)N_NODES * D];  // A2 = agg(A1)
__device__ __align__(16) int g_slot[(size_t)N_NODES * CAP]; // bucketed src ids
__device__ int   g_cnt[N_NODES];                            // degree / cursor
__device__ float g_W2[D * D];                  // W @ W
__device__ float g_bW[D];                      // b @ W^T
__device__ int   g_is64;

// ---------------------------------------------------------------------------
// Fused init: blocks [0,98) zero g_cnt; [98,114) compute W2; 114: bW + detect.
// ---------------------------------------------------------------------------
__global__ void init2_kernel(const unsigned* __restrict__ ei,
                             const float* __restrict__ W,
                             const float* __restrict__ b) {
    int t = threadIdx.x;                 // 256
    int bid = blockIdx.x;
    if (bid < ZBLKS) {
        int i4 = bid * 1024 + t * 4;
        if (i4 < N_NODES)
            *reinterpret_cast<int4*>(&g_cnt[i4]) = make_int4(0, 0, 0, 0);
        return;
    }
    __shared__ float Wsh[D * D];
    #pragma unroll
    for (int i = t; i < D * D; i += 256) Wsh[i] = W[i];
    __syncthreads();
    if (bid < ZBLKS + 16) {
        int o = (bid - ZBLKS) * 256 + t;
        int j = o >> 6, k = o & 63;
        float s = 0.f;
        #pragma unroll
        for (int m = 0; m < D; m++) s += Wsh[j * D + m] * Wsh[m * D + k];
        g_W2[o] = s;
    } else {
        if (t < D) {
            float s = 0.f;
            #pragma unroll
            for (int k = 0; k < D; k++) s += b[k] * Wsh[t * D + k];
            g_bW[t] = s;
        } else if (t == 64) {
            int all0 = 1;
            #pragma unroll 1
            for (int k = 0; k < 64; k++) {
                if (ei[2 * k + 1] != 0u) { all0 = 0; break; }
            }
            g_is64 = all0;
        }
    }
}

// ---------------------------------------------------------------------------
// One-pass bucket fill: slot[dst*CAP + pos] = src. 8 edges/thread.
// ---------------------------------------------------------------------------
__global__ void bucket_kernel(const void* __restrict__ ei) {
    int q = blockIdx.x * blockDim.x + threadIdx.x;
    int e = q * 8;
    if (e >= N_EDGES) return;
    int s[8], d[8];
    if (g_is64) {
        const longlong2* ps = reinterpret_cast<const longlong2*>((const long long*)ei + e);
        const longlong2* pd = reinterpret_cast<const longlong2*>((const long long*)ei + N_EDGES + e);
        #pragma unroll
        for (int i = 0; i < 4; i++) {
            longlong2 a = __ldg(ps + i);
            longlong2 u = __ldg(pd + i);
            s[2 * i] = (int)a.x; s[2 * i + 1] = (int)a.y;
            d[2 * i] = (int)u.x; d[2 * i + 1] = (int)u.y;
        }
    } else {
        const int4* ps = reinterpret_cast<const int4*>((const int*)ei + e);
        const int4* pd = reinterpret_cast<const int4*>((const int*)ei + N_EDGES + e);
        #pragma unroll
        for (int i = 0; i < 2; i++) {
            int4 a = __ldg(ps + i);
            int4 u = __ldg(pd + i);
            s[4 * i] = a.x; s[4 * i + 1] = a.y; s[4 * i + 2] = a.z; s[4 * i + 3] = a.w;
            d[4 * i] = u.x; d[4 * i + 1] = u.y; d[4 * i + 2] = u.z; d[4 * i + 3] = u.w;
        }
    }
    int p[8];
    #pragma unroll
    for (int i = 0; i < 8; i++) p[i] = atomicAdd(&g_cnt[d[i]], 1);
    #pragma unroll
    for (int i = 0; i < 8; i++)
        if (p[i] < CAP) g_slot[(size_t)d[i] * CAP + p[i]] = s[i];
}

// ---------------------------------------------------------------------------
// Gather (fp32): phase 0: x -> g_a1, phase 1: g_a1 -> g_a2.
// 16 lanes per node (one float4 each). Slot indices loaded 4-at-a-time via
// int4 (CAP is int4-aligned); 4 independent row loads per group -> high MLP
// without a per-edge dependent idx->row chain.
// ---------------------------------------------------------------------------
__global__ void gather_kernel(const float* __restrict__ x, int phase) {
    int t = blockIdx.x * blockDim.x + threadIdx.x;
    int node = t >> 4;
    int c = t & 15;
    if (node >= N_NODES) return;

    const float* in = phase ? g_a1 : x;
    float* outp     = phase ? g_a2 : g_a1;

    int cnt = __ldg(&g_cnt[node]);
    if (cnt > CAP) cnt = CAP;
    const int4* slots4 = reinterpret_cast<const int4*>(g_slot + (size_t)node * CAP);
    const int ngroups = (cnt + 3) >> 2;

    float4 acc = make_float4(0.f, 0.f, 0.f, 0.f);
    #pragma unroll 2
    for (int q = 0; q < ngroups; q++) {
        int4 s = __ldg(&slots4[q]);
        int base = q * 4;
        if (base + 0 < cnt) {
            float4 v = *reinterpret_cast<const float4*>(in + (size_t)s.x * D + c * 4);
            acc.x += v.x; acc.y += v.y; acc.z += v.z; acc.w += v.w;
        }
        if (base + 1 < cnt) {
            float4 v = *reinterpret_cast<const float4*>(in + (size_t)s.y * D + c * 4);
            acc.x += v.x; acc.y += v.y; acc.z += v.z; acc.w += v.w;
        }
        if (base + 2 < cnt) {
            float4 v = *reinterpret_cast<const float4*>(in + (size_t)s.z * D + c * 4);
            acc.x += v.x; acc.y += v.y; acc.z += v.z; acc.w += v.w;
        }
        if (base + 3 < cnt) {
            float4 v = *reinterpret_cast<const float4*>(in + (size_t)s.w * D + c * 4);
            acc.x += v.x; acc.y += v.y; acc.z += v.z; acc.w += v.w;
        }
    }
    *reinterpret_cast<float4*>(outp + (size_t)node * D + c * 4) = acc;
}

// ---------------------------------------------------------------------------
// Dual GEMM per 64-row tile:
//   phase 1:  hid = A1 @ W^T  + b
//   phase 2:  out = A2 @ W2^T + deg*bW + b
// 4x4 register tile, fma.rn.f32x2 (FFMA2).
// ---------------------------------------------------------------------------
#define SROW 68

__device__ __forceinline__ void stage_a_tile(float* As, const float* __restrict__ src,
                                             int row0, int t) {
    #pragma unroll
    for (int i = t; i < 64 * 16; i += 256) {
        int r = i >> 4, k4 = i & 15;
        int row = row0 + r;
        float4 v = make_float4(0.f, 0.f, 0.f, 0.f);
        if (row < N_NODES)
            v = reinterpret_cast<const float4*>(src)[(size_t)row * 16 + k4];
        *reinterpret_cast<float4*>(&As[r * SROW + k4 * 4]) = v;
    }
}

__device__ __forceinline__ void gemm_tile(const float* As, const float* Ws,
                                          unsigned long long acc[4][4],
                                          int tx, int ty) {
    #pragma unroll 4
    for (int k4 = 0; k4 < 16; k4++) {
        ulonglong2 a[4], w[4];
        #pragma unroll
        for (int ri = 0; ri < 4; ri++)
            a[ri] = *reinterpret_cast<const ulonglong2*>(&As[(ty * 4 + ri) * SROW + k4 * 4]);
        #pragma unroll
        for (int ji = 0; ji < 4; ji++)
            w[ji] = *reinterpret_cast<const ulonglong2*>(&Ws[(tx + 16 * ji) * SROW + k4 * 4]);
        #pragma unroll
        for (int ri = 0; ri < 4; ri++)
            #pragma unroll
            for (int ji = 0; ji < 4; ji++) {
                asm("fma.rn.f32x2 %0, %1, %2, %0;"
                    : "+l"(acc[ri][ji]) : "l"(a[ri].x), "l"(w[ji].x));
                asm("fma.rn.f32x2 %0, %1, %2, %0;"
                    : "+l"(acc[ri][ji]) : "l"(a[ri].y), "l"(w[ji].y));
            }
    }
}

__global__ __launch_bounds__(256) void dual_linear_kernel(
        float* __restrict__ hid, float* __restrict__ out,
        const float* __restrict__ W, const float* __restrict__ b) {
    __shared__ __align__(16) float As[64 * SROW];
    __shared__ __align__(16) float Ws[64 * SROW];

    const int t = threadIdx.x;           // 256 threads
    const int row0 = blockIdx.x * 64;
    const int tx = t & 15;
    const int ty = t >> 4;

    // ---- phase 1: hid = A1 @ W^T + b ----
    #pragma unroll
    for (int i = t; i < 64 * 16; i += 256) {
        int j = i >> 4, k4 = i & 15;
        *reinterpret_cast<float4*>(&Ws[j * SROW + k4 * 4]) =
            reinterpret_cast<const float4*>(W)[j * 16 + k4];
    }
    stage_a_tile(As, g_a1, row0, t);
    __syncthreads();

    {
        unsigned long long acc[4][4];
        #pragma unroll
        for (int ri = 0; ri < 4; ri++)
            #pragma unroll
            for (int ji = 0; ji < 4; ji++) acc[ri][ji] = 0ull;
        gemm_tile(As, Ws, acc, tx, ty);
        float bj[4];
        #pragma unroll
        for (int ji = 0; ji < 4; ji++) bj[ji] = __ldg(&b[tx + 16 * ji]);
        #pragma unroll
        for (int ri = 0; ri < 4; ri++) {
            int row = row0 + ty * 4 + ri;
            if (row < N_NODES) {
                #pragma unroll
                for (int ji = 0; ji < 4; ji++) {
                    float lo, hi;
                    asm("mov.b64 {%0, %1}, %2;" : "=f"(lo), "=f"(hi) : "l"(acc[ri][ji]));
                    hid[(size_t)row * D + tx + 16 * ji] = lo + hi + bj[ji];
                }
            }
        }
    }
    __syncthreads();

    // ---- phase 2: out = A2 @ W2^T + deg*bW + b ----
    #pragma unroll
    for (int i = t; i < 64 * 16; i += 256) {
        int j = i >> 4, k4 = i & 15;
        *reinterpret_cast<float4*>(&Ws[j * SROW + k4 * 4]) =
            reinterpret_cast<const float4*>(g_W2)[j * 16 + k4];
    }
    stage_a_tile(As, g_a2, row0, t);
    __syncthreads();

    {
        unsigned long long acc[4][4];
        #pragma unroll
        for (int ri = 0; ri < 4; ri++)
            #pragma unroll
            for (int ji = 0; ji < 4; ji++) acc[ri][ji] = 0ull;
        gemm_tile(As, Ws, acc, tx, ty);
        float bj[4], bWj[4];
        #pragma unroll
        for (int ji = 0; ji < 4; ji++) {
            bj[ji]  = __ldg(&b[tx + 16 * ji]);
            bWj[ji] = __ldg(&g_bW[tx + 16 * ji]);
        }
        #pragma unroll
        for (int ri = 0; ri < 4; ri++) {
            int row = row0 + ty * 4 + ri;
            if (row < N_NODES) {
                float degf = __int2float_rn(__ldg(&g_cnt[row]));
                #pragma unroll
                for (int ji = 0; ji < 4; ji++) {
                    float lo, hi;
                    asm("mov.b64 {%0, %1}, %2;" : "=f"(lo), "=f"(hi) : "l"(acc[ri][ji]));
                    out[(size_t)row * D + tx + 16 * ji] = lo + hi + degf * bWj[ji] + bj[ji];
                }
            }
        }
    }
}

// ---------------------------------------------------------------------------
extern "C" void kernel_launch(void* const* d_in, const int* in_sizes, int n_in,
                              void* d_out, int out_size) {
    const float* x  = (const float*)d_in[0];
    const void*  ei = d_in[1];
    const float* W1 = (const float*)d_in[2];
    const float* b1 = (const float*)d_in[3];

    float* out = (float*)d_out;                      // (out, hid) flattened
    float* hid = out + (size_t)N_NODES * D;

    const int E8BLK = (N_EDGES / 8 + 255) / 256;     // 611
    const int GBLK  = (N_NODES * 16 + 255) / 256;    // 6250
    const int FBLK  = (N_NODES + 63) / 64;           // 1563

    init2_kernel<<<ZBLKS + 17, 256>>>((const unsigned*)ei, W1, b1);
    bucket_kernel<<<E8BLK, 256>>>(ei);
    gather_kernel<<<GBLK, 256>>>(x, 0);              // A1 = agg(x)
    gather_kernel<<<GBLK, 256>>>(x, 1);              // A2 = agg(A1)
    dual_linear_kernel<<<FBLK, 256>>>(hid, out, W1, b1);
}